// round 10
// baseline (speedup 1.0000x reference)
#include <cuda_runtime.h>
#include <cuda_fp16.h>
#include <cstdint>

#define BSZN 8
#define HD   512
#define PD   128
#define LEN  8192
#define M2   256

// ---------------- scratch (no allocations allowed) ----------------
__device__ __align__(128) float g_bu[(size_t)BSZN * M2 * LEN];      // 64 MB (Bu, fp32)
__device__ __align__(128) __half g_uhi[(size_t)BSZN * HD * LEN];    // 64 MB hi
__device__ __align__(128) __half g_ulo[(size_t)BSZN * HD * LEN];    // lo
__device__ __align__(128) __half g_xhi[(size_t)BSZN * M2 * LEN];
__device__ __align__(128) __half g_xlo[(size_t)BSZN * M2 * LEN];
__device__ __align__(128) __half g_w1h[M2 * HD];                    // weights: fp16 hi only
__device__ __align__(128) __half g_w2h[HD * M2];
__device__ float g_lam_re[PD];
__device__ float g_lam_im[PD];

// ---------------- helpers ----------------
__device__ __forceinline__ uint32_t smem_u32(const void* p) {
    uint32_t a;
    asm("{ .reg .u64 t; cvta.to.shared.u64 t, %1; cvt.u32.u64 %0, t; }" : "=r"(a) : "l"(p));
    return a;
}
__device__ __forceinline__ float gelu_exact(float x) {
    return 0.5f * x * (1.0f + erff(x * 0.70710678118654752f));
}
__device__ __forceinline__ void ldsm_x4(uint32_t (&r)[4], uint32_t addr) {
    asm volatile("ldmatrix.sync.aligned.m8n8.x4.shared.b16 {%0,%1,%2,%3}, [%4];"
                 : "=r"(r[0]), "=r"(r[1]), "=r"(r[2]), "=r"(r[3]) : "r"(addr));
}
__device__ __forceinline__ void ldsm_x4_t(uint32_t (&r)[4], uint32_t addr) {
    asm volatile("ldmatrix.sync.aligned.m8n8.x4.trans.shared.b16 {%0,%1,%2,%3}, [%4];"
                 : "=r"(r[0]), "=r"(r[1]), "=r"(r[2]), "=r"(r[3]) : "r"(addr));
}
__device__ __forceinline__ void mma_fp16(float (&c)[4], const uint32_t (&a)[4],
                                         const uint32_t* b) {
    asm volatile("mma.sync.aligned.m16n8k16.row.col.f32.f16.f16.f32 "
                 "{%0,%1,%2,%3},{%4,%5,%6,%7},{%8,%9},{%0,%1,%2,%3};"
                 : "+f"(c[0]), "+f"(c[1]), "+f"(c[2]), "+f"(c[3])
                 : "r"(a[0]), "r"(a[1]), "r"(a[2]), "r"(a[3]), "r"(b[0]), "r"(b[1]));
}
__device__ __forceinline__ void cp16(uint32_t saddr, const void* g) {
    asm volatile("cp.async.cg.shared.global [%0], [%1], 16;" :: "r"(saddr), "l"(g));
}
#define CP_COMMIT() asm volatile("cp.async.commit_group;" ::: "memory")
#define CP_WAIT2()  asm volatile("cp.async.wait_group 2;" ::: "memory")

// ---------------------------------------------------------------------------
// Precompute: Lambda_bar; weights as single fp16 (hi).
//   W1 = [Re(B_bar); Im(B_bar)]  (2P x H)   W2 = [2*C_re | -2*C_im] (H x 2P)
// ---------------------------------------------------------------------------
__global__ void precompute_kernel(const float* __restrict__ lre,
                                  const float* __restrict__ lim,
                                  const float* __restrict__ Bp,
                                  const float* __restrict__ Cp,
                                  const float* __restrict__ ls) {
    int idx = blockIdx.x * blockDim.x + threadIdx.x;   // [0, 65536)
    {   // W1: p = idx>>9, hcol = idx&511
        int p = idx >> 9, hcol = idx & 511;
        float ar = lre[p], ai = lim[p];
        float st = expf(ls[p]);
        float er = expf(ar * st);
        float sb, cb; sincosf(ai * st, &sb, &cb);
        float lbr = er * cb, lbi = er * sb;
        float nr = lbr - 1.0f, ni = lbi;
        float den = ar * ar + ai * ai;
        float cr = (nr * ar + ni * ai) / den;
        float ci = (ni * ar - nr * ai) / den;
        float btr = Bp[(p * HD + hcol) * 2 + 0];
        float bti = Bp[(p * HD + hcol) * 2 + 1];
        g_w1h[p * HD + hcol]        = __float2half_rn(cr * btr - ci * bti);
        g_w1h[(p + PD) * HD + hcol] = __float2half_rn(cr * bti + ci * btr);
    }
    if (idx < PD) {
        float ar = lre[idx], ai = lim[idx];
        float st = expf(ls[idx]);
        float er = expf(ar * st);
        float sb, cb; sincosf(ai * st, &sb, &cb);
        g_lam_re[idx] = er * cb;
        g_lam_im[idx] = er * sb;
    }
    {   // W2: hrow = idx>>7, p = idx&127
        int hrow = idx >> 7, p = idx & 127;
        g_w2h[hrow * M2 + p]      = __float2half_rn( 2.0f * Cp[(hrow * PD + p) * 2 + 0]);
        g_w2h[hrow * M2 + p + PD] = __float2half_rn(-2.0f * Cp[(hrow * PD + p) * 2 + 1]);
    }
}

// ---------------------------------------------------------------------------
// Convert u (fp32) -> fp16 hi/lo arrays. 33.5M elems, float4 per thread.
// ---------------------------------------------------------------------------
__global__ __launch_bounds__(256)
void conv_u_kernel(const float* __restrict__ u) {
    size_t i = ((size_t)blockIdx.x * 256 + threadIdx.x) * 4;
    float4 v = *(const float4*)&u[i];
    __half h0 = __float2half_rn(v.x), h1 = __float2half_rn(v.y);
    __half h2 = __float2half_rn(v.z), h3 = __float2half_rn(v.w);
    __half l0 = __float2half_rn(v.x - __half2float(h0));
    __half l1 = __float2half_rn(v.y - __half2float(h1));
    __half l2 = __float2half_rn(v.z - __half2float(h2));
    __half l3 = __float2half_rn(v.w - __half2float(h3));
    ushort4 hw = make_ushort4(__half_as_ushort(h0), __half_as_ushort(h1),
                              __half_as_ushort(h2), __half_as_ushort(h3));
    ushort4 lw = make_ushort4(__half_as_ushort(l0), __half_as_ushort(l1),
                              __half_as_ushort(l2), __half_as_ushort(l3));
    *(ushort4*)&g_uhi[i] = hw;
    *(ushort4*)&g_ulo[i] = lw;
}

// ---------------------------------------------------------------------------
// mma.sync fp16 GEMM, 2-product split (Wh*Xh + Wh*Xl), cp.async 4-stage pipe.
// CTA tile 128x128, K-chunk 32, 8 warps (4m x 2n), warp tile 32x64.
// Stage: A(8K) Bhi(8K) Blo(8K) = 24KB; 4 stages = 96KB; 2 CTAs/SM.
// ---------------------------------------------------------------------------
#define ABUF   8192
#define BUFSZ  24576
#define STAGES 4
#define GSMEM  (STAGES * BUFSZ)

template<bool SECOND>
__global__ __launch_bounds__(256, 2)
void mgemm_kernel(const __half* __restrict__ Bhi_g,
                  const __half* __restrict__ Blo_g,
                  const float* __restrict__ uin,
                  float* __restrict__ outp,
                  const float* __restrict__ Dvec) {
    constexpr int KDIM = SECOND ? M2 : HD;
    constexpr int NCH  = KDIM / 32;

    extern __shared__ __align__(128) char smem[];
    const uint32_t sbase = smem_u32(smem);

    const int tid  = threadIdx.x;
    const int wid  = tid >> 5;
    const int lane = tid & 31;
    const int warp_m = wid & 3;
    const int warp_n = wid >> 2;
    const int m0 = blockIdx.x * 128;
    const int n0 = blockIdx.y * 128;
    const int z  = blockIdx.z;

    const __half* Wh = SECOND ? g_w2h : g_w1h;
    float* Cdst = SECOND ? outp : (float*)g_bu;
    const size_t Bofs = (size_t)z * KDIM * LEN;
    const size_t Cofs = (size_t)z * (SECOND ? HD : M2) * LEN;

    // staging maps (fixed per thread)
    const int sAr = tid >> 1, sAh = tid & 1;       // A: row 0..127, k-half (16 elems)
    const int sBk = tid >> 3, sBn = tid & 7;       // B: k-row 0..31, 16-wide n group
    const int aswz = (sAr >> 1) & 3;
    const int bswz = sBk & 7;
    const uint32_t aoff0 = (uint32_t)(sAr * 64 + (((sAh * 2 + 0) ^ aswz) << 4));
    const uint32_t aoff1 = (uint32_t)(sAr * 64 + (((sAh * 2 + 1) ^ aswz) << 4));
    const uint32_t boff0 = (uint32_t)(ABUF + sBk * 256 + (((sBn * 2 + 0) ^ bswz) << 4));
    const uint32_t boff1 = (uint32_t)(ABUF + sBk * 256 + (((sBn * 2 + 1) ^ bswz) << 4));

    auto issue_commit = [&](int ci) {
        if (ci < NCH) {
            const int k0 = ci * 32;
            const uint32_t bb = sbase + (uint32_t)(ci % STAGES) * BUFSZ;
            const __half* gA = Wh + (size_t)(m0 + sAr) * KDIM + k0 + sAh * 16;
            cp16(bb + aoff0, gA);
            cp16(bb + aoff1, gA + 8);
            const size_t go = Bofs + (size_t)(k0 + sBk) * LEN + n0 + sBn * 16;
            cp16(bb + boff0, Bhi_g + go);
            cp16(bb + boff1, Bhi_g + go + 8);
            cp16(bb + ABUF + boff0, Blo_g + go);
            cp16(bb + ABUF + boff1, Blo_g + go + 8);
        }
        CP_COMMIT();
    };

    float acc[2][8][4];
    #pragma unroll
    for (int a = 0; a < 2; a++)
        #pragma unroll
        for (int b = 0; b < 8; b++)
            #pragma unroll
            for (int c = 0; c < 4; c++) acc[a][b][c] = 0.0f;

    const int lrow8 = (lane & 7) + ((lane >> 3) & 1) * 8;   // 0..15
    const int lhalf = (lane >> 4) & 1;                      // 0/1

    auto compute = [&](uint32_t bb) {
        #pragma unroll
        for (int ks = 0; ks < 2; ks++) {
            uint32_t Am[2][4];
            #pragma unroll
            for (int mt = 0; mt < 2; mt++) {
                int row = warp_m * 32 + mt * 16 + lrow8;
                int c = ks * 2 + lhalf;
                uint32_t addr = sbase + bb + row * 64 + ((c ^ ((row >> 1) & 3)) << 4);
                ldsm_x4(Am[mt], addr);
            }
            #pragma unroll
            for (int nt = 0; nt < 4; nt++) {
                int krow = ks * 16 + lrow8;
                int noff = warp_n * 64 + nt * 16 + lhalf * 8;
                int c = noff >> 3;
                uint32_t addr = sbase + bb + ABUF + krow * 256 +
                                ((c ^ (krow & 7)) << 4);
                uint32_t Bh[4], Bl[4];
                ldsm_x4_t(Bh, addr);
                ldsm_x4_t(Bl, addr + ABUF);
                #pragma unroll
                for (int mt = 0; mt < 2; mt++) {
                    mma_fp16(acc[mt][2*nt + 0], Am[mt], &Bh[0]);
                    mma_fp16(acc[mt][2*nt + 0], Am[mt], &Bl[0]);
                    mma_fp16(acc[mt][2*nt + 1], Am[mt], &Bh[2]);
                    mma_fp16(acc[mt][2*nt + 1], Am[mt], &Bl[2]);
                }
            }
        }
    };

    issue_commit(0);
    issue_commit(1);
    issue_commit(2);
    for (int i = 0; i < NCH; i++) {
        CP_WAIT2();               // group for chunk i complete (i+1, i+2 in flight)
        __syncthreads();
        issue_commit(i + 3);      // refills slot (i-1)%4; safe: all warps past compute(i-1)
        compute((uint32_t)(i % STAGES) * BUFSZ);
    }

    // ---------------- epilogue ----------------
    const int g = lane >> 2, t4 = lane & 3;
    #pragma unroll
    for (int mt = 0; mt < 2; mt++) {
        #pragma unroll
        for (int nt8 = 0; nt8 < 8; nt8++) {
            int col = n0 + warp_n * 64 + nt8 * 8 + t4 * 2;
            #pragma unroll
            for (int h = 0; h < 2; h++) {
                int row = m0 + warp_m * 32 + mt * 16 + g + h * 8;
                size_t off = Cofs + (size_t)row * LEN + col;
                float v0 = acc[mt][nt8][2*h + 0];
                float v1 = acc[mt][nt8][2*h + 1];
                if (SECOND) {
                    float d = __ldg(&Dvec[row]);
                    float2 uu = *(const float2*)&uin[(size_t)z * HD * LEN +
                                                     (size_t)row * LEN + col];
                    v0 = gelu_exact(v0 + d * uu.x);
                    v1 = gelu_exact(v1 + d * uu.y);
                }
                float2 st; st.x = v0; st.y = v1;
                *(float2*)&Cdst[off] = st;
            }
        }
    }
}

// ---------------------------------------------------------------------------
// Scan: x_l = a*x_{l-1} + b_l, complex diagonal, one block per (b,p) channel.
// Reads Bu fp32 from g_bu; writes xs as fp16 hi/lo for GEMM2.
// ---------------------------------------------------------------------------
__global__ __launch_bounds__(256)
void scan_kernel() {
    int ch = blockIdx.x;
    int b = ch >> 7, p = ch & 127;
    const float ar = g_lam_re[p];
    const float ai = g_lam_im[p];

    const size_t rre = ((size_t)b * M2 + p) * LEN;
    const size_t rim = ((size_t)b * M2 + p + PD) * LEN;
    const float* bre = g_bu + rre;
    const float* bim = g_bu + rim;

    __shared__ float sre[2112], sim[2112];
    __shared__ float vre[256], vim[256];
    __shared__ float carry_re, carry_im;

    int t = threadIdx.x;
    if (t == 0) { carry_re = 0.0f; carry_im = 0.0f; }

    float mr[8], mi[8];
    {
        float xr = ar, xi = ai;
        #pragma unroll
        for (int s = 0; s < 3; s++) {
            float nr = xr * xr - xi * xi;
            float ni = 2.0f * xr * xi;
            xr = nr; xi = ni;
        }
        mr[0] = xr; mi[0] = xi;
        #pragma unroll
        for (int k = 1; k < 8; k++) {
            mr[k] = mr[k-1] * mr[k-1] - mi[k-1] * mi[k-1];
            mi[k] = 2.0f * mr[k-1] * mi[k-1];
        }
    }
    __syncthreads();

    const int base = t * 8;
    for (int c0 = 0; c0 < LEN; c0 += 2048) {
        for (int j = t; j < 2048; j += 256) {
            sre[j + (j >> 5)] = bre[c0 + j];
            sim[j + (j >> 5)] = bim[c0 + j];
        }
        __syncthreads();

        float er = 0.0f, ei = 0.0f;
        if (t == 0) { er = carry_re; ei = carry_im; }
        #pragma unroll
        for (int i = 0; i < 8; i++) {
            int idx = base + i; idx += idx >> 5;
            float br = sre[idx], bi = sim[idx];
            float nr = ar * er - ai * ei + br;
            float ni = ar * ei + ai * er + bi;
            er = nr; ei = ni;
        }
        vre[t] = er; vim[t] = ei;
        __syncthreads();

        #pragma unroll
        for (int k = 0; k < 8; k++) {
            int off = 1 << k;
            float pr = 0.0f, pi = 0.0f;
            if (t >= off) { pr = vre[t - off]; pi = vim[t - off]; }
            __syncthreads();
            if (t >= off) {
                vre[t] += mr[k] * pr - mi[k] * pi;
                vim[t] += mr[k] * pi + mi[k] * pr;
            }
            __syncthreads();
        }

        float xr, xi;
        if (t == 0) { xr = carry_re; xi = carry_im; }
        else        { xr = vre[t-1]; xi = vim[t-1]; }
        #pragma unroll
        for (int i = 0; i < 8; i++) {
            int idx = base + i; idx += idx >> 5;
            float br = sre[idx], bi = sim[idx];
            float nr = ar * xr - ai * xi + br;
            float ni = ar * xi + ai * xr + bi;
            xr = nr; xi = ni;
            sre[idx] = xr; sim[idx] = xi;
        }
        __syncthreads();

        if (t == 0) { carry_re = vre[255]; carry_im = vim[255]; }
        // writeback: convert to fp16 hi/lo
        for (int j = t; j < 2048; j += 256) {
            float xr2 = sre[j + (j >> 5)];
            float xi2 = sim[j + (j >> 5)];
            __half hr = __float2half_rn(xr2);
            __half hi = __float2half_rn(xi2);
            g_xhi[rre + c0 + j] = hr;
            g_xhi[rim + c0 + j] = hi;
            g_xlo[rre + c0 + j] = __float2half_rn(xr2 - __half2float(hr));
            g_xlo[rim + c0 + j] = __float2half_rn(xi2 - __half2float(hi));
        }
        __syncthreads();
    }
}

// ---------------------------------------------------------------------------
extern "C" void kernel_launch(void* const* d_in, const int* in_sizes, int n_in,
                              void* d_out, int out_size) {
    const float* u   = (const float*)d_in[0];   // (8,1,512,1,8192)
    const float* lre = (const float*)d_in[1];
    const float* lim = (const float*)d_in[2];
    const float* B   = (const float*)d_in[3];
    const float* C   = (const float*)d_in[4];
    const float* D   = (const float*)d_in[5];
    const float* ls  = (const float*)d_in[6];
    float* out = (float*)d_out;

    cudaFuncSetAttribute(mgemm_kernel<false>,
                         cudaFuncAttributeMaxDynamicSharedMemorySize, GSMEM);
    cudaFuncSetAttribute(mgemm_kernel<true>,
                         cudaFuncAttributeMaxDynamicSharedMemorySize, GSMEM);

    __half *uhi, *ulo, *xhi, *xlo;
    cudaGetSymbolAddress((void**)&uhi, g_uhi);
    cudaGetSymbolAddress((void**)&ulo, g_ulo);
    cudaGetSymbolAddress((void**)&xhi, g_xhi);
    cudaGetSymbolAddress((void**)&xlo, g_xlo);

    precompute_kernel<<<256, 256>>>(lre, lim, B, C, ls);
    conv_u_kernel<<<32768, 256>>>(u);   // 32768*256*4 = 33.5M = BSZN*HD*LEN
    mgemm_kernel<false><<<dim3(2, 64, BSZN), 256, GSMEM>>>(uhi, ulo, u, nullptr, nullptr);
    scan_kernel<<<1024, 256>>>();
    mgemm_kernel<true><<<dim3(4, 64, BSZN), 256, GSMEM>>>(xhi, xlo, u, out, D);
}

// round 11
// speedup vs baseline: 1.5595x; 1.5595x over previous
#include <cuda_runtime.h>
#include <cuda_fp16.h>
#include <cstdint>

#define BSZN 8
#define HD   512
#define PD   128
#define LEN  8192
#define M2   256

// ---------------- scratch (no allocations allowed) ----------------
__device__ __align__(128) float g_bu[(size_t)BSZN * M2 * LEN];      // 64 MB (Bu, fp32)
__device__ __align__(128) __half g_uhi[(size_t)BSZN * HD * LEN];
__device__ __align__(128) __half g_ulo[(size_t)BSZN * HD * LEN];
__device__ __align__(128) __half g_xhi[(size_t)BSZN * M2 * LEN];
__device__ __align__(128) __half g_xlo[(size_t)BSZN * M2 * LEN];
__device__ __align__(128) __half g_w1h[M2 * HD];                    // weights fp16
__device__ __align__(128) __half g_w2h[HD * M2];
__device__ float g_lam_re[PD];
__device__ float g_lam_im[PD];

// ---------------- helpers ----------------
__device__ __forceinline__ uint32_t smem_u32(const void* p) {
    uint32_t a;
    asm("{ .reg .u64 t; cvta.to.shared.u64 t, %1; cvt.u32.u64 %0, t; }" : "=r"(a) : "l"(p));
    return a;
}
__device__ __forceinline__ float gelu_exact(float x) {
    return 0.5f * x * (1.0f + erff(x * 0.70710678118654752f));
}
__device__ __forceinline__ void ldsm_x4(uint32_t (&r)[4], uint32_t addr) {
    asm volatile("ldmatrix.sync.aligned.m8n8.x4.shared.b16 {%0,%1,%2,%3}, [%4];"
                 : "=r"(r[0]), "=r"(r[1]), "=r"(r[2]), "=r"(r[3]) : "r"(addr));
}
__device__ __forceinline__ void ldsm_x4_t(uint32_t (&r)[4], uint32_t addr) {
    asm volatile("ldmatrix.sync.aligned.m8n8.x4.trans.shared.b16 {%0,%1,%2,%3}, [%4];"
                 : "=r"(r[0]), "=r"(r[1]), "=r"(r[2]), "=r"(r[3]) : "r"(addr));
}
__device__ __forceinline__ void mma_fp16(float (&c)[4], const uint32_t (&a)[4],
                                         const uint32_t* b) {
    asm volatile("mma.sync.aligned.m16n8k16.row.col.f32.f16.f16.f32 "
                 "{%0,%1,%2,%3},{%4,%5,%6,%7},{%8,%9},{%0,%1,%2,%3};"
                 : "+f"(c[0]), "+f"(c[1]), "+f"(c[2]), "+f"(c[3])
                 : "r"(a[0]), "r"(a[1]), "r"(a[2]), "r"(a[3]), "r"(b[0]), "r"(b[1]));
}
__device__ __forceinline__ void cp16(uint32_t saddr, const void* g) {
    asm volatile("cp.async.cg.shared.global [%0], [%1], 16;" :: "r"(saddr), "l"(g));
}
#define CP_COMMIT() asm volatile("cp.async.commit_group;" ::: "memory")
#define CP_WAIT1()  asm volatile("cp.async.wait_group 1;" ::: "memory")

// ---------------------------------------------------------------------------
// Precompute: Lambda_bar; weights as fp16.
//   W1 = [Re(B_bar); Im(B_bar)]  (2P x H)   W2 = [2*C_re | -2*C_im] (H x 2P)
// ---------------------------------------------------------------------------
__global__ void precompute_kernel(const float* __restrict__ lre,
                                  const float* __restrict__ lim,
                                  const float* __restrict__ Bp,
                                  const float* __restrict__ Cp,
                                  const float* __restrict__ ls) {
    int idx = blockIdx.x * blockDim.x + threadIdx.x;   // [0, 65536)
    {   // W1: p = idx>>9, hcol = idx&511
        int p = idx >> 9, hcol = idx & 511;
        float ar = lre[p], ai = lim[p];
        float st = expf(ls[p]);
        float er = expf(ar * st);
        float sb, cb; sincosf(ai * st, &sb, &cb);
        float lbr = er * cb, lbi = er * sb;
        float nr = lbr - 1.0f, ni = lbi;
        float den = ar * ar + ai * ai;
        float cr = (nr * ar + ni * ai) / den;
        float ci = (ni * ar - nr * ai) / den;
        float btr = Bp[(p * HD + hcol) * 2 + 0];
        float bti = Bp[(p * HD + hcol) * 2 + 1];
        g_w1h[p * HD + hcol]        = __float2half_rn(cr * btr - ci * bti);
        g_w1h[(p + PD) * HD + hcol] = __float2half_rn(cr * bti + ci * btr);
    }
    if (idx < PD) {
        float ar = lre[idx], ai = lim[idx];
        float st = expf(ls[idx]);
        float er = expf(ar * st);
        float sb, cb; sincosf(ai * st, &sb, &cb);
        g_lam_re[idx] = er * cb;
        g_lam_im[idx] = er * sb;
    }
    {   // W2: hrow = idx>>7, p = idx&127
        int hrow = idx >> 7, p = idx & 127;
        g_w2h[hrow * M2 + p]      = __float2half_rn( 2.0f * Cp[(hrow * PD + p) * 2 + 0]);
        g_w2h[hrow * M2 + p + PD] = __float2half_rn(-2.0f * Cp[(hrow * PD + p) * 2 + 1]);
    }
}

// ---------------------------------------------------------------------------
// Convert u (fp32) -> fp16 hi/lo arrays. 33.5M elems, float4 per thread.
// ---------------------------------------------------------------------------
__global__ __launch_bounds__(256)
void conv_u_kernel(const float* __restrict__ u) {
    size_t i = ((size_t)blockIdx.x * 256 + threadIdx.x) * 4;
    float4 v = *(const float4*)&u[i];
    __half h0 = __float2half_rn(v.x), h1 = __float2half_rn(v.y);
    __half h2 = __float2half_rn(v.z), h3 = __float2half_rn(v.w);
    __half l0 = __float2half_rn(v.x - __half2float(h0));
    __half l1 = __float2half_rn(v.y - __half2float(h1));
    __half l2 = __float2half_rn(v.z - __half2float(h2));
    __half l3 = __float2half_rn(v.w - __half2float(h3));
    ushort4 hw = make_ushort4(__half_as_ushort(h0), __half_as_ushort(h1),
                              __half_as_ushort(h2), __half_as_ushort(h3));
    ushort4 lw = make_ushort4(__half_as_ushort(l0), __half_as_ushort(l1),
                              __half_as_ushort(l2), __half_as_ushort(l3));
    *(ushort4*)&g_uhi[i] = hw;
    *(ushort4*)&g_ulo[i] = lw;
}

// ---------------------------------------------------------------------------
// mma.sync fp16 GEMM, 2-product split (W*Xh + W*Xl), R8-proven cp.async pipe:
// 3 stages, wait_group 1, compute-then-issue.
// CTA tile 128x128, K-chunk 32, 8 warps (4m x 2n), warp tile 32x64.
// Stage: A(8K) Bhi(8K) Blo(8K) = 24KB; 3 stages = 72KB; 2 CTAs/SM.
// ---------------------------------------------------------------------------
#define ABUF   8192
#define BUFSZ  24576
#define STAGES 3
#define GSMEM  (STAGES * BUFSZ)

template<bool SECOND>
__global__ __launch_bounds__(256, 2)
void mgemm_kernel(const __half* __restrict__ Bhi_g,
                  const __half* __restrict__ Blo_g,
                  const float* __restrict__ uin,
                  float* __restrict__ outp,
                  const float* __restrict__ Dvec) {
    constexpr int KDIM = SECOND ? M2 : HD;
    constexpr int NCH  = KDIM / 32;

    extern __shared__ __align__(128) char smem[];
    const uint32_t sbase = smem_u32(smem);

    const int tid  = threadIdx.x;
    const int wid  = tid >> 5;
    const int lane = tid & 31;
    const int warp_m = wid & 3;
    const int warp_n = wid >> 2;
    const int m0 = blockIdx.x * 128;
    const int n0 = blockIdx.y * 128;
    const int z  = blockIdx.z;

    const __half* Wh = SECOND ? g_w2h : g_w1h;
    float* Cdst = SECOND ? outp : (float*)g_bu;
    const size_t Bofs = (size_t)z * KDIM * LEN;
    const size_t Cofs = (size_t)z * (SECOND ? HD : M2) * LEN;

    // staging maps (fixed per thread)
    const int sAr = tid >> 1, sAh = tid & 1;       // A: row 0..127, k-half (16 elems)
    const int sBk = tid >> 3, sBn = tid & 7;       // B: k-row 0..31, 16-wide n group
    const int aswz = (sAr >> 1) & 3;
    const int bswz = sBk & 7;
    const uint32_t aoff0 = (uint32_t)(sAr * 64 + (((sAh * 2 + 0) ^ aswz) << 4));
    const uint32_t aoff1 = (uint32_t)(sAr * 64 + (((sAh * 2 + 1) ^ aswz) << 4));
    const uint32_t boff0 = (uint32_t)(ABUF + sBk * 256 + (((sBn * 2 + 0) ^ bswz) << 4));
    const uint32_t boff1 = (uint32_t)(ABUF + sBk * 256 + (((sBn * 2 + 1) ^ bswz) << 4));

    auto issue_commit = [&](int ci) {
        if (ci < NCH) {
            const int k0 = ci * 32;
            const uint32_t bb = sbase + (uint32_t)(ci % STAGES) * BUFSZ;
            const __half* gA = Wh + (size_t)(m0 + sAr) * KDIM + k0 + sAh * 16;
            cp16(bb + aoff0, gA);
            cp16(bb + aoff1, gA + 8);
            const size_t go = Bofs + (size_t)(k0 + sBk) * LEN + n0 + sBn * 16;
            cp16(bb + boff0, Bhi_g + go);
            cp16(bb + boff1, Bhi_g + go + 8);
            cp16(bb + ABUF + boff0, Blo_g + go);
            cp16(bb + ABUF + boff1, Blo_g + go + 8);
        }
        CP_COMMIT();
    };

    float acc[2][8][4];
    #pragma unroll
    for (int a = 0; a < 2; a++)
        #pragma unroll
        for (int b = 0; b < 8; b++)
            #pragma unroll
            for (int c = 0; c < 4; c++) acc[a][b][c] = 0.0f;

    const int lrow8 = (lane & 7) + ((lane >> 3) & 1) * 8;   // 0..15
    const int lhalf = (lane >> 4) & 1;                      // 0/1

    auto compute = [&](uint32_t bb) {
        #pragma unroll
        for (int ks = 0; ks < 2; ks++) {
            uint32_t Am[2][4];
            #pragma unroll
            for (int mt = 0; mt < 2; mt++) {
                int row = warp_m * 32 + mt * 16 + lrow8;
                int c = ks * 2 + lhalf;
                uint32_t addr = sbase + bb + row * 64 + ((c ^ ((row >> 1) & 3)) << 4);
                ldsm_x4(Am[mt], addr);
            }
            #pragma unroll
            for (int nt = 0; nt < 4; nt++) {
                int krow = ks * 16 + lrow8;
                int noff = warp_n * 64 + nt * 16 + lhalf * 8;
                int c = noff >> 3;
                uint32_t addr = sbase + bb + ABUF + krow * 256 +
                                ((c ^ (krow & 7)) << 4);
                uint32_t Bh[4], Bl[4];
                ldsm_x4_t(Bh, addr);
                ldsm_x4_t(Bl, addr + ABUF);
                #pragma unroll
                for (int mt = 0; mt < 2; mt++) {
                    mma_fp16(acc[mt][2*nt + 0], Am[mt], &Bh[0]);
                    mma_fp16(acc[mt][2*nt + 0], Am[mt], &Bl[0]);
                    mma_fp16(acc[mt][2*nt + 1], Am[mt], &Bh[2]);
                    mma_fp16(acc[mt][2*nt + 1], Am[mt], &Bl[2]);
                }
            }
        }
    };

    issue_commit(0);
    issue_commit(1);
    for (int i = 0; i < NCH; i++) {
        CP_WAIT1();               // group for chunk i complete
        __syncthreads();
        compute((uint32_t)(i % STAGES) * BUFSZ);
        issue_commit(i + 2);      // refills slot (i-1)%3, consumed at iter i-1
    }

    // ---------------- epilogue ----------------
    const int g = lane >> 2, t4 = lane & 3;
    #pragma unroll
    for (int mt = 0; mt < 2; mt++) {
        #pragma unroll
        for (int nt8 = 0; nt8 < 8; nt8++) {
            int col = n0 + warp_n * 64 + nt8 * 8 + t4 * 2;
            #pragma unroll
            for (int h = 0; h < 2; h++) {
                int row = m0 + warp_m * 32 + mt * 16 + g + h * 8;
                size_t off = Cofs + (size_t)row * LEN + col;
                float v0 = acc[mt][nt8][2*h + 0];
                float v1 = acc[mt][nt8][2*h + 1];
                if (SECOND) {
                    float d = __ldg(&Dvec[row]);
                    float2 uu = *(const float2*)&uin[(size_t)z * HD * LEN +
                                                     (size_t)row * LEN + col];
                    v0 = gelu_exact(v0 + d * uu.x);
                    v1 = gelu_exact(v1 + d * uu.y);
                }
                float2 st; st.x = v0; st.y = v1;
                *(float2*)&Cdst[off] = st;
            }
        }
    }
}

// ---------------------------------------------------------------------------
// Scan: x_l = a*x_{l-1} + b_l, complex diagonal, one block per (b,p) channel.
// Reads Bu fp32 from g_bu; writes xs as fp16 hi/lo for GEMM2.
// ---------------------------------------------------------------------------
__global__ __launch_bounds__(256)
void scan_kernel() {
    int ch = blockIdx.x;
    int b = ch >> 7, p = ch & 127;
    const float ar = g_lam_re[p];
    const float ai = g_lam_im[p];

    const size_t rre = ((size_t)b * M2 + p) * LEN;
    const size_t rim = ((size_t)b * M2 + p + PD) * LEN;
    const float* bre = g_bu + rre;
    const float* bim = g_bu + rim;

    __shared__ float sre[2112], sim[2112];
    __shared__ float vre[256], vim[256];
    __shared__ float carry_re, carry_im;

    int t = threadIdx.x;
    if (t == 0) { carry_re = 0.0f; carry_im = 0.0f; }

    float mr[8], mi[8];
    {
        float xr = ar, xi = ai;
        #pragma unroll
        for (int s = 0; s < 3; s++) {
            float nr = xr * xr - xi * xi;
            float ni = 2.0f * xr * xi;
            xr = nr; xi = ni;
        }
        mr[0] = xr; mi[0] = xi;
        #pragma unroll
        for (int k = 1; k < 8; k++) {
            mr[k] = mr[k-1] * mr[k-1] - mi[k-1] * mi[k-1];
            mi[k] = 2.0f * mr[k-1] * mi[k-1];
        }
    }
    __syncthreads();

    const int base = t * 8;
    for (int c0 = 0; c0 < LEN; c0 += 2048) {
        for (int j = t; j < 2048; j += 256) {
            sre[j + (j >> 5)] = bre[c0 + j];
            sim[j + (j >> 5)] = bim[c0 + j];
        }
        __syncthreads();

        float er = 0.0f, ei = 0.0f;
        if (t == 0) { er = carry_re; ei = carry_im; }
        #pragma unroll
        for (int i = 0; i < 8; i++) {
            int idx = base + i; idx += idx >> 5;
            float br = sre[idx], bi = sim[idx];
            float nr = ar * er - ai * ei + br;
            float ni = ar * ei + ai * er + bi;
            er = nr; ei = ni;
        }
        vre[t] = er; vim[t] = ei;
        __syncthreads();

        #pragma unroll
        for (int k = 0; k < 8; k++) {
            int off = 1 << k;
            float pr = 0.0f, pi = 0.0f;
            if (t >= off) { pr = vre[t - off]; pi = vim[t - off]; }
            __syncthreads();
            if (t >= off) {
                vre[t] += mr[k] * pr - mi[k] * pi;
                vim[t] += mr[k] * pi + mi[k] * pr;
            }
            __syncthreads();
        }

        float xr, xi;
        if (t == 0) { xr = carry_re; xi = carry_im; }
        else        { xr = vre[t-1]; xi = vim[t-1]; }
        #pragma unroll
        for (int i = 0; i < 8; i++) {
            int idx = base + i; idx += idx >> 5;
            float br = sre[idx], bi = sim[idx];
            float nr = ar * xr - ai * xi + br;
            float ni = ar * xi + ai * xr + bi;
            xr = nr; xi = ni;
            sre[idx] = xr; sim[idx] = xi;
        }
        __syncthreads();

        if (t == 0) { carry_re = vre[255]; carry_im = vim[255]; }
        // writeback: convert to fp16 hi/lo
        for (int j = t; j < 2048; j += 256) {
            float xr2 = sre[j + (j >> 5)];
            float xi2 = sim[j + (j >> 5)];
            __half hr = __float2half_rn(xr2);
            __half hi = __float2half_rn(xi2);
            g_xhi[rre + c0 + j] = hr;
            g_xhi[rim + c0 + j] = hi;
            g_xlo[rre + c0 + j] = __float2half_rn(xr2 - __half2float(hr));
            g_xlo[rim + c0 + j] = __float2half_rn(xi2 - __half2float(hi));
        }
        __syncthreads();
    }
}

// ---------------------------------------------------------------------------
extern "C" void kernel_launch(void* const* d_in, const int* in_sizes, int n_in,
                              void* d_out, int out_size) {
    const float* u   = (const float*)d_in[0];   // (8,1,512,1,8192)
    const float* lre = (const float*)d_in[1];
    const float* lim = (const float*)d_in[2];
    const float* B   = (const float*)d_in[3];
    const float* C   = (const float*)d_in[4];
    const float* D   = (const float*)d_in[5];
    const float* ls  = (const float*)d_in[6];
    float* out = (float*)d_out;

    cudaFuncSetAttribute(mgemm_kernel<false>,
                         cudaFuncAttributeMaxDynamicSharedMemorySize, GSMEM);
    cudaFuncSetAttribute(mgemm_kernel<true>,
                         cudaFuncAttributeMaxDynamicSharedMemorySize, GSMEM);

    __half *uhi, *ulo, *xhi, *xlo;
    cudaGetSymbolAddress((void**)&uhi, g_uhi);
    cudaGetSymbolAddress((void**)&ulo, g_ulo);
    cudaGetSymbolAddress((void**)&xhi, g_xhi);
    cudaGetSymbolAddress((void**)&xlo, g_xlo);

    precompute_kernel<<<256, 256>>>(lre, lim, B, C, ls);
    conv_u_kernel<<<32768, 256>>>(u);   // 32768*256*4 = 33.5M = BSZN*HD*LEN
    mgemm_kernel<false><<<dim3(2, 64, BSZN), 256, GSMEM>>>(uhi, ulo, u, nullptr, nullptr);
    scan_kernel<<<1024, 256>>>();
    mgemm_kernel<true><<<dim3(4, 64, BSZN), 256, GSMEM>>>(xhi, xlo, u, out, D);
}

// round 12
// speedup vs baseline: 2.0784x; 1.3327x over previous
#include <cuda_runtime.h>
#include <cuda_fp16.h>
#include <cstdint>

#define BSZN 8
#define HD   512
#define PD   128
#define LEN  8192
#define M2   256

// ---------------- scratch (no allocations allowed) ----------------
__device__ __align__(128) float g_bu[(size_t)BSZN * M2 * LEN];      // 64 MB (Bu, fp32)
__device__ __align__(128) __half g_uhi[(size_t)BSZN * HD * LEN];    // u  as fp16
__device__ __align__(128) __half g_xhi[(size_t)BSZN * M2 * LEN];    // xs as fp16
__device__ __align__(128) __half g_w1h[M2 * HD];                    // weights fp16
__device__ __align__(128) __half g_w2h[HD * M2];
__device__ float g_lam_re[PD];
__device__ float g_lam_im[PD];

// ---------------- helpers ----------------
__device__ __forceinline__ uint32_t smem_u32(const void* p) {
    uint32_t a;
    asm("{ .reg .u64 t; cvta.to.shared.u64 t, %1; cvt.u32.u64 %0, t; }" : "=r"(a) : "l"(p));
    return a;
}
__device__ __forceinline__ float gelu_exact(float x) {
    return 0.5f * x * (1.0f + erff(x * 0.70710678118654752f));
}
__device__ __forceinline__ void ldsm_x4(uint32_t (&r)[4], uint32_t addr) {
    asm volatile("ldmatrix.sync.aligned.m8n8.x4.shared.b16 {%0,%1,%2,%3}, [%4];"
                 : "=r"(r[0]), "=r"(r[1]), "=r"(r[2]), "=r"(r[3]) : "r"(addr));
}
__device__ __forceinline__ void ldsm_x4_t(uint32_t (&r)[4], uint32_t addr) {
    asm volatile("ldmatrix.sync.aligned.m8n8.x4.trans.shared.b16 {%0,%1,%2,%3}, [%4];"
                 : "=r"(r[0]), "=r"(r[1]), "=r"(r[2]), "=r"(r[3]) : "r"(addr));
}
__device__ __forceinline__ void mma_fp16(float (&c)[4], const uint32_t (&a)[4],
                                         const uint32_t* b) {
    asm volatile("mma.sync.aligned.m16n8k16.row.col.f32.f16.f16.f32 "
                 "{%0,%1,%2,%3},{%4,%5,%6,%7},{%8,%9},{%0,%1,%2,%3};"
                 : "+f"(c[0]), "+f"(c[1]), "+f"(c[2]), "+f"(c[3])
                 : "r"(a[0]), "r"(a[1]), "r"(a[2]), "r"(a[3]), "r"(b[0]), "r"(b[1]));
}
__device__ __forceinline__ void cp16(uint32_t saddr, const void* g) {
    asm volatile("cp.async.cg.shared.global [%0], [%1], 16;" :: "r"(saddr), "l"(g));
}
#define CP_COMMIT() asm volatile("cp.async.commit_group;" ::: "memory")
#define CP_WAIT1()  asm volatile("cp.async.wait_group 1;" ::: "memory")

// ---------------------------------------------------------------------------
// Precompute: Lambda_bar; weights as fp16.
//   W1 = [Re(B_bar); Im(B_bar)]  (2P x H)   W2 = [2*C_re | -2*C_im] (H x 2P)
// ---------------------------------------------------------------------------
__global__ void precompute_kernel(const float* __restrict__ lre,
                                  const float* __restrict__ lim,
                                  const float* __restrict__ Bp,
                                  const float* __restrict__ Cp,
                                  const float* __restrict__ ls) {
    int idx = blockIdx.x * blockDim.x + threadIdx.x;   // [0, 65536)
    {   // W1: p = idx>>9, hcol = idx&511
        int p = idx >> 9, hcol = idx & 511;
        float ar = lre[p], ai = lim[p];
        float st = expf(ls[p]);
        float er = expf(ar * st);
        float sb, cb; sincosf(ai * st, &sb, &cb);
        float lbr = er * cb, lbi = er * sb;
        float nr = lbr - 1.0f, ni = lbi;
        float den = ar * ar + ai * ai;
        float cr = (nr * ar + ni * ai) / den;
        float ci = (ni * ar - nr * ai) / den;
        float btr = Bp[(p * HD + hcol) * 2 + 0];
        float bti = Bp[(p * HD + hcol) * 2 + 1];
        g_w1h[p * HD + hcol]        = __float2half_rn(cr * btr - ci * bti);
        g_w1h[(p + PD) * HD + hcol] = __float2half_rn(cr * bti + ci * btr);
    }
    if (idx < PD) {
        float ar = lre[idx], ai = lim[idx];
        float st = expf(ls[idx]);
        float er = expf(ar * st);
        float sb, cb; sincosf(ai * st, &sb, &cb);
        g_lam_re[idx] = er * cb;
        g_lam_im[idx] = er * sb;
    }
    {   // W2: hrow = idx>>7, p = idx&127
        int hrow = idx >> 7, p = idx & 127;
        g_w2h[hrow * M2 + p]      = __float2half_rn( 2.0f * Cp[(hrow * PD + p) * 2 + 0]);
        g_w2h[hrow * M2 + p + PD] = __float2half_rn(-2.0f * Cp[(hrow * PD + p) * 2 + 1]);
    }
}

// ---------------------------------------------------------------------------
// Convert u (fp32) -> fp16. 33.5M elems, float4 per thread.
// ---------------------------------------------------------------------------
__global__ __launch_bounds__(256)
void conv_u_kernel(const float* __restrict__ u) {
    size_t i = ((size_t)blockIdx.x * 256 + threadIdx.x) * 4;
    float4 v = *(const float4*)&u[i];
    ushort4 hw = make_ushort4(__half_as_ushort(__float2half_rn(v.x)),
                              __half_as_ushort(__float2half_rn(v.y)),
                              __half_as_ushort(__float2half_rn(v.z)),
                              __half_as_ushort(__float2half_rn(v.w)));
    *(ushort4*)&g_uhi[i] = hw;
}

// ---------------------------------------------------------------------------
// mma.sync fp16 GEMM, single product, R8-proven cp.async pipe:
// 3 stages, wait_group 1, compute-then-issue.
// CTA tile 128x128, K-chunk 32, 8 warps (4m x 2n), warp tile 32x64.
// Stage: A(8K) B(8K) = 16KB; 3 stages = 48KB; 2 CTAs/SM.
// ---------------------------------------------------------------------------
#define ABUF   8192
#define BUFSZ  16384
#define STAGES 3
#define GSMEM  (STAGES * BUFSZ)

template<bool SECOND>
__global__ __launch_bounds__(256, 2)
void mgemm_kernel(const __half* __restrict__ Bhi_g,
                  const float* __restrict__ uin,
                  float* __restrict__ outp,
                  const float* __restrict__ Dvec) {
    constexpr int KDIM = SECOND ? M2 : HD;
    constexpr int NCH  = KDIM / 32;

    extern __shared__ __align__(128) char smem[];
    const uint32_t sbase = smem_u32(smem);

    const int tid  = threadIdx.x;
    const int wid  = tid >> 5;
    const int lane = tid & 31;
    const int warp_m = wid & 3;
    const int warp_n = wid >> 2;
    const int m0 = blockIdx.x * 128;
    const int n0 = blockIdx.y * 128;
    const int z  = blockIdx.z;

    const __half* Wh = SECOND ? g_w2h : g_w1h;
    float* Cdst = SECOND ? outp : (float*)g_bu;
    const size_t Bofs = (size_t)z * KDIM * LEN;
    const size_t Cofs = (size_t)z * (SECOND ? HD : M2) * LEN;

    // staging maps (fixed per thread)
    const int sAr = tid >> 1, sAh = tid & 1;       // A: row 0..127, k-half (16 elems)
    const int sBk = tid >> 3, sBn = tid & 7;       // B: k-row 0..31, 16-wide n group
    const int aswz = (sAr >> 1) & 3;
    const int bswz = sBk & 7;
    const uint32_t aoff0 = (uint32_t)(sAr * 64 + (((sAh * 2 + 0) ^ aswz) << 4));
    const uint32_t aoff1 = (uint32_t)(sAr * 64 + (((sAh * 2 + 1) ^ aswz) << 4));
    const uint32_t boff0 = (uint32_t)(ABUF + sBk * 256 + (((sBn * 2 + 0) ^ bswz) << 4));
    const uint32_t boff1 = (uint32_t)(ABUF + sBk * 256 + (((sBn * 2 + 1) ^ bswz) << 4));

    auto issue_commit = [&](int ci) {
        if (ci < NCH) {
            const int k0 = ci * 32;
            const uint32_t bb = sbase + (uint32_t)(ci % STAGES) * BUFSZ;
            const __half* gA = Wh + (size_t)(m0 + sAr) * KDIM + k0 + sAh * 16;
            cp16(bb + aoff0, gA);
            cp16(bb + aoff1, gA + 8);
            const size_t go = Bofs + (size_t)(k0 + sBk) * LEN + n0 + sBn * 16;
            cp16(bb + boff0, Bhi_g + go);
            cp16(bb + boff1, Bhi_g + go + 8);
        }
        CP_COMMIT();
    };

    float acc[2][8][4];
    #pragma unroll
    for (int a = 0; a < 2; a++)
        #pragma unroll
        for (int b = 0; b < 8; b++)
            #pragma unroll
            for (int c = 0; c < 4; c++) acc[a][b][c] = 0.0f;

    const int lrow8 = (lane & 7) + ((lane >> 3) & 1) * 8;   // 0..15
    const int lhalf = (lane >> 4) & 1;                      // 0/1

    auto compute = [&](uint32_t bb) {
        #pragma unroll
        for (int ks = 0; ks < 2; ks++) {
            uint32_t Am[2][4];
            #pragma unroll
            for (int mt = 0; mt < 2; mt++) {
                int row = warp_m * 32 + mt * 16 + lrow8;
                int c = ks * 2 + lhalf;
                uint32_t addr = sbase + bb + row * 64 + ((c ^ ((row >> 1) & 3)) << 4);
                ldsm_x4(Am[mt], addr);
            }
            #pragma unroll
            for (int nt = 0; nt < 4; nt++) {
                int krow = ks * 16 + lrow8;
                int noff = warp_n * 64 + nt * 16 + lhalf * 8;
                int c = noff >> 3;
                uint32_t addr = sbase + bb + ABUF + krow * 256 +
                                ((c ^ (krow & 7)) << 4);
                uint32_t Bh[4];
                ldsm_x4_t(Bh, addr);
                #pragma unroll
                for (int mt = 0; mt < 2; mt++) {
                    mma_fp16(acc[mt][2*nt + 0], Am[mt], &Bh[0]);
                    mma_fp16(acc[mt][2*nt + 1], Am[mt], &Bh[2]);
                }
            }
        }
    };

    issue_commit(0);
    issue_commit(1);
    for (int i = 0; i < NCH; i++) {
        CP_WAIT1();               // group for chunk i complete
        __syncthreads();
        compute((uint32_t)(i % STAGES) * BUFSZ);
        issue_commit(i + 2);      // refills slot (i-1)%3, consumed at iter i-1
    }

    // ---------------- epilogue ----------------
    const int g = lane >> 2, t4 = lane & 3;
    #pragma unroll
    for (int mt = 0; mt < 2; mt++) {
        #pragma unroll
        for (int nt8 = 0; nt8 < 8; nt8++) {
            int col = n0 + warp_n * 64 + nt8 * 8 + t4 * 2;
            #pragma unroll
            for (int h = 0; h < 2; h++) {
                int row = m0 + warp_m * 32 + mt * 16 + g + h * 8;
                size_t off = Cofs + (size_t)row * LEN + col;
                float v0 = acc[mt][nt8][2*h + 0];
                float v1 = acc[mt][nt8][2*h + 1];
                if (SECOND) {
                    float d = __ldg(&Dvec[row]);
                    float2 uu = *(const float2*)&uin[(size_t)z * HD * LEN +
                                                     (size_t)row * LEN + col];
                    v0 = gelu_exact(v0 + d * uu.x);
                    v1 = gelu_exact(v1 + d * uu.y);
                }
                float2 st; st.x = v0; st.y = v1;
                *(float2*)&Cdst[off] = st;
            }
        }
    }
}

// ---------------------------------------------------------------------------
// Scan: x_l = a*x_{l-1} + b_l, complex diagonal, one block per (b,p) channel.
// Reads Bu fp32 from g_bu; writes xs as fp16 for GEMM2.
// ---------------------------------------------------------------------------
__global__ __launch_bounds__(256)
void scan_kernel() {
    int ch = blockIdx.x;
    int b = ch >> 7, p = ch & 127;
    const float ar = g_lam_re[p];
    const float ai = g_lam_im[p];

    const size_t rre = ((size_t)b * M2 + p) * LEN;
    const size_t rim = ((size_t)b * M2 + p + PD) * LEN;
    const float* bre = g_bu + rre;
    const float* bim = g_bu + rim;

    __shared__ float sre[2112], sim[2112];
    __shared__ float vre[256], vim[256];
    __shared__ float carry_re, carry_im;

    int t = threadIdx.x;
    if (t == 0) { carry_re = 0.0f; carry_im = 0.0f; }

    float mr[8], mi[8];
    {
        float xr = ar, xi = ai;
        #pragma unroll
        for (int s = 0; s < 3; s++) {
            float nr = xr * xr - xi * xi;
            float ni = 2.0f * xr * xi;
            xr = nr; xi = ni;
        }
        mr[0] = xr; mi[0] = xi;
        #pragma unroll
        for (int k = 1; k < 8; k++) {
            mr[k] = mr[k-1] * mr[k-1] - mi[k-1] * mi[k-1];
            mi[k] = 2.0f * mr[k-1] * mi[k-1];
        }
    }
    __syncthreads();

    const int base = t * 8;
    for (int c0 = 0; c0 < LEN; c0 += 2048) {
        for (int j = t; j < 2048; j += 256) {
            sre[j + (j >> 5)] = bre[c0 + j];
            sim[j + (j >> 5)] = bim[c0 + j];
        }
        __syncthreads();

        float er = 0.0f, ei = 0.0f;
        if (t == 0) { er = carry_re; ei = carry_im; }
        #pragma unroll
        for (int i = 0; i < 8; i++) {
            int idx = base + i; idx += idx >> 5;
            float br = sre[idx], bi = sim[idx];
            float nr = ar * er - ai * ei + br;
            float ni = ar * ei + ai * er + bi;
            er = nr; ei = ni;
        }
        vre[t] = er; vim[t] = ei;
        __syncthreads();

        #pragma unroll
        for (int k = 0; k < 8; k++) {
            int off = 1 << k;
            float pr = 0.0f, pi = 0.0f;
            if (t >= off) { pr = vre[t - off]; pi = vim[t - off]; }
            __syncthreads();
            if (t >= off) {
                vre[t] += mr[k] * pr - mi[k] * pi;
                vim[t] += mr[k] * pi + mi[k] * pr;
            }
            __syncthreads();
        }

        float xr, xi;
        if (t == 0) { xr = carry_re; xi = carry_im; }
        else        { xr = vre[t-1]; xi = vim[t-1]; }
        #pragma unroll
        for (int i = 0; i < 8; i++) {
            int idx = base + i; idx += idx >> 5;
            float br = sre[idx], bi = sim[idx];
            float nr = ar * xr - ai * xi + br;
            float ni = ar * xi + ai * xr + bi;
            xr = nr; xi = ni;
            sre[idx] = xr; sim[idx] = xi;
        }
        __syncthreads();

        if (t == 0) { carry_re = vre[255]; carry_im = vim[255]; }
        // writeback: convert to fp16
        for (int j = t; j < 2048; j += 256) {
            g_xhi[rre + c0 + j] = __float2half_rn(sre[j + (j >> 5)]);
            g_xhi[rim + c0 + j] = __float2half_rn(sim[j + (j >> 5)]);
        }
        __syncthreads();
    }
}

// ---------------------------------------------------------------------------
extern "C" void kernel_launch(void* const* d_in, const int* in_sizes, int n_in,
                              void* d_out, int out_size) {
    const float* u   = (const float*)d_in[0];   // (8,1,512,1,8192)
    const float* lre = (const float*)d_in[1];
    const float* lim = (const float*)d_in[2];
    const float* B   = (const float*)d_in[3];
    const float* C   = (const float*)d_in[4];
    const float* D   = (const float*)d_in[5];
    const float* ls  = (const float*)d_in[6];
    float* out = (float*)d_out;

    cudaFuncSetAttribute(mgemm_kernel<false>,
                         cudaFuncAttributeMaxDynamicSharedMemorySize, GSMEM);
    cudaFuncSetAttribute(mgemm_kernel<true>,
                         cudaFuncAttributeMaxDynamicSharedMemorySize, GSMEM);

    __half *uhi, *xhi;
    cudaGetSymbolAddress((void**)&uhi, g_uhi);
    cudaGetSymbolAddress((void**)&xhi, g_xhi);

    precompute_kernel<<<256, 256>>>(lre, lim, B, C, ls);
    conv_u_kernel<<<32768, 256>>>(u);   // 32768*256*4 = 33.5M = BSZN*HD*LEN
    mgemm_kernel<false><<<dim3(2, 64, BSZN), 256, GSMEM>>>(uhi, u, nullptr, nullptr);
    scan_kernel<<<1024, 256>>>();
    mgemm_kernel<true><<<dim3(4, 64, BSZN), 256, GSMEM>>>(xhi, u, out, D);
}